// round 6
// baseline (speedup 1.0000x reference)
#include <cuda_runtime.h>
#include <cuda_fp16.h>
#include <math.h>
#include <stdint.h>

// Problem shape (fixed): B=8, T=2048, D=1024
#define BB   8
#define TT   2048
#define DD   1024
#define MM   (BB*TT)          // 16384 rows
#define NCHUNK 32
#define CHLEN  64

// Fused GEMM tiling: CTA 128(M)x128(N), 2 outputs, warp 64x32x2, BK=32, K=1024
#define BKE    32             // K elements per chunk (64B rows in smem)
#define NCH    (DD / BKE)     // 32 chunks
#define A_OFF  0
#define BZ_OFF 8192
#define BH_OFF 16384
#define STAGE_B 24576          // 24KB per stage (A + Bz + Bh)

// ---------------- scratch (device globals) ----------------
__device__ float g_a[(size_t)MM * DD];
__device__ float g_b[(size_t)MM * DD];
__device__ float g_Ac[BB * NCHUNK * DD];
__device__ float g_Bc[BB * NCHUNK * DD];

__device__ __half g_xh[(size_t)MM * DD];    // x in fp16
__device__ __half g_Wtz[DD * DD];           // Wz^T in fp16: [n][k]
__device__ __half g_Wth[DD * DD];           // Wh^T in fp16: [n][k]

__device__ __forceinline__ float sigmoidf_fast(float v) {
    return 1.0f / (1.0f + __expf(-v));
}

// ---------------- PTX helpers ----------------
__device__ __forceinline__ uint32_t smem_u32(const void* p) {
    uint32_t a;
    asm("{ .reg .u64 t; cvta.to.shared.u64 t, %1; cvt.u32.u64 %0, t; }" : "=r"(a) : "l"(p));
    return a;
}
#define SWZ64(o) ((o) ^ (((o) >> 3) & 0x30))

__device__ __forceinline__ void cp16(uint32_t s, const void* g) {
    asm volatile("cp.async.cg.shared.global [%0], [%1], 16;" :: "r"(s), "l"(g));
}
__device__ __forceinline__ void cp_commit() {
    asm volatile("cp.async.commit_group;" ::: "memory");
}
__device__ __forceinline__ void ldsm_x4(uint32_t& r0, uint32_t& r1, uint32_t& r2,
                                        uint32_t& r3, uint32_t addr) {
    asm volatile("ldmatrix.sync.aligned.m8n8.x4.shared.b16 {%0,%1,%2,%3}, [%4];"
                 : "=r"(r0), "=r"(r1), "=r"(r2), "=r"(r3) : "r"(addr));
}
__device__ __forceinline__ void mma_f16(float* d, const uint32_t* a, const uint32_t* b) {
    asm volatile(
        "mma.sync.aligned.m16n8k16.row.col.f32.f16.f16.f32 "
        "{%0,%1,%2,%3},{%4,%5,%6,%7},{%8,%9},{%0,%1,%2,%3};"
        : "+f"(d[0]), "+f"(d[1]), "+f"(d[2]), "+f"(d[3])
        : "r"(a[0]), "r"(a[1]), "r"(a[2]), "r"(a[3]), "r"(b[0]), "r"(b[1]));
}

// ---------------- prep: convert x to fp16 ----------------
__global__ __launch_bounds__(256)
void convert_x_kernel(const float* __restrict__ x)
{
    const size_t i4 = (size_t)blockIdx.x * 256 + threadIdx.x;
    const float4 v = ((const float4*)x)[i4];
    __half2 p0, p1;
    p0.x = __float2half_rn(v.x); p0.y = __float2half_rn(v.y);
    p1.x = __float2half_rn(v.z); p1.y = __float2half_rn(v.w);
    ((__half2*)g_xh)[i4 * 2]     = p0;
    ((__half2*)g_xh)[i4 * 2 + 1] = p1;
}

// ---------------- prep: transpose W -> Wt[n][k], fp16 ----------------
__global__ __launch_bounds__(256)
void transpose_kernel(const float* __restrict__ Wz, const float* __restrict__ Wh)
{
    __shared__ float sm[32][33];
    const float* W = (blockIdx.z == 0) ? Wz : Wh;
    __half* Wt = (blockIdx.z == 0) ? g_Wtz : g_Wth;

    const int k0 = blockIdx.y * 32;
    const int n0 = blockIdx.x * 32;
    const int r = threadIdx.x >> 5;
    const int c = threadIdx.x & 31;
#pragma unroll
    for (int rr = 0; rr < 4; rr++) {
        const int row = rr * 8 + r;
        sm[row][c] = W[(size_t)(k0 + row) * DD + n0 + c];
    }
    __syncthreads();
#pragma unroll
    for (int rr = 0; rr < 4; rr++) {
        const int row = rr * 8 + r;
        Wt[(size_t)(n0 + row) * DD + k0 + c] = __float2half_rn(sm[c][row]);
    }
}

// ---------------- fused HMMA GEMM: zlin = x@Wz, hlin = x@Wh ------------------
// epilogue: z = sig(zlin+bz); g_a = 1-z; g_b = z*(hlin+bh).
// Template on pipeline depth NST (power of 2). 4-stage needs 96KB dynamic smem
// (set via cudaFuncSetAttribute); 2-stage fits the 48KB default as fallback.
template <int NST>
__global__ __launch_bounds__(256, 1)
void gemm_fused_kernel(const float* __restrict__ bz, const float* __restrict__ bh)
{
    extern __shared__ char smem[];
    const uint32_t sbase = smem_u32(smem);
    const int tid  = threadIdx.x;
    const int wid  = tid >> 5;
    const int lane = tid & 31;
    const int wr = wid >> 2;           // warp row 0..1 (64 M-rows each)
    const int wc = wid & 3;            // warp col 0..3 (32 N-cols each)

    const int nBase = blockIdx.x * 128;
    const int mBase = blockIdx.y * 128;

    // ---- cp.async static addressing: per region, 2x 16B per thread ----
    int ldRow[2];
    int ldCol[2];
    uint32_t ldOff[2];
#pragma unroll
    for (int t = 0; t < 2; t++) {
        const int o = tid + t * 256;
        ldRow[t] = o >> 2;             // 128 rows x 4 chunks of 16B (64B rows)
        ldCol[t] = o & 3;
        ldOff[t] = SWZ64((uint32_t)(o * 16));
    }

    // ---- ldmatrix static offsets ----
    const int quad = lane >> 3;
    const int r8   = lane & 7;
    const int rowA = (quad & 1) * 8 + r8;
    const int kbA  = (quad >> 1) * 16;
    const int rowB = (quad >> 1) * 8 + r8;
    const int kbB  = (quad & 1) * 16;

    uint32_t offA[2][4], offB[2][2];   // offB relative to B region start
#pragma unroll
    for (int ks = 0; ks < 2; ks++) {
#pragma unroll
        for (int mt = 0; mt < 4; mt++)
            offA[ks][mt] = SWZ64((uint32_t)((wr * 64 + mt * 16 + rowA) * 64 + ks * 32 + kbA));
#pragma unroll
        for (int bt = 0; bt < 2; bt++)
            offB[ks][bt] = SWZ64((uint32_t)((wc * 32 + bt * 16 + rowB) * 64 + ks * 32 + kbB));
    }

    float accz[4][4][4], acch[4][4][4];
#pragma unroll
    for (int i = 0; i < 4; i++)
#pragma unroll
        for (int j = 0; j < 4; j++)
#pragma unroll
            for (int k = 0; k < 4; k++) { accz[i][j][k] = 0.0f; acch[i][j][k] = 0.0f; }

    auto load_chunk = [&](int chunk, int stage) {
        const int k0 = chunk * BKE;
        const uint32_t st = sbase + stage * STAGE_B;
#pragma unroll
        for (int t = 0; t < 2; t++) {
            const size_t rowOff = (size_t)ldRow[t] * DD + k0 + ldCol[t] * 8;
            cp16(st + A_OFF  + ldOff[t], g_xh  + (size_t)mBase * DD + rowOff);
            cp16(st + BZ_OFF + ldOff[t], g_Wtz + (size_t)nBase * DD + rowOff);
            cp16(st + BH_OFF + ldOff[t], g_Wth + (size_t)nBase * DD + rowOff);
        }
        cp_commit();
    };

    // prologue: NST-1 chunks in flight
#pragma unroll
    for (int p = 0; p < NST - 1; p++) load_chunk(p, p);

    for (int i = 0; i < NCH; i++) {
        const int s = i & (NST - 1);
        // ensure chunk i's group has completed. Outstanding groups at loop
        // top = min(NST-1, NCH-i); chunk i done when <= (that-1) remain.
        int pend = NCH - 1 - i;
        if (pend > NST - 2) pend = NST - 2;
        if (pend >= 2)      asm volatile("cp.async.wait_group 2;" ::: "memory");
        else if (pend == 1) asm volatile("cp.async.wait_group 1;" ::: "memory");
        else                asm volatile("cp.async.wait_group 0;" ::: "memory");
        // sync AFTER wait, BEFORE next load: all warps are done reading stage
        // (i-1)&(NST-1) (iteration i-1's compute), and chunk i's smem writes
        // become visible to all warps.
        __syncthreads();
        if (i + NST - 1 < NCH) load_chunk(i + NST - 1, (i + NST - 1) & (NST - 1));

        const uint32_t st = sbase + s * STAGE_B;
#pragma unroll
        for (int ks = 0; ks < 2; ks++) {
            uint32_t af[4][4];
#pragma unroll
            for (int mt = 0; mt < 4; mt++)
                ldsm_x4(af[mt][0], af[mt][1], af[mt][2], af[mt][3],
                        st + A_OFF + offA[ks][mt]);
            // ---- z output ----
            {
                uint32_t bf[4][2];
#pragma unroll
                for (int bt = 0; bt < 2; bt++)
                    ldsm_x4(bf[bt*2][0], bf[bt*2][1], bf[bt*2+1][0], bf[bt*2+1][1],
                            st + BZ_OFF + offB[ks][bt]);
#pragma unroll
                for (int mt = 0; mt < 4; mt++)
#pragma unroll
                    for (int nt = 0; nt < 4; nt++)
                        mma_f16(accz[mt][nt], af[mt], bf[nt]);
            }
            // ---- h output ----
            {
                uint32_t bf[4][2];
#pragma unroll
                for (int bt = 0; bt < 2; bt++)
                    ldsm_x4(bf[bt*2][0], bf[bt*2][1], bf[bt*2+1][0], bf[bt*2+1][1],
                            st + BH_OFF + offB[ks][bt]);
#pragma unroll
                for (int mt = 0; mt < 4; mt++)
#pragma unroll
                    for (int nt = 0; nt < 4; nt++)
                        mma_f16(acch[mt][nt], af[mt], bf[nt]);
            }
        }
    }

    // ---- epilogue: a = 1-z, b = z*(hlin+bh) directly from fragments ----
    const int er = lane >> 2;
    const int ec = (lane & 3) * 2;
#pragma unroll
    for (int mt = 0; mt < 4; mt++) {
#pragma unroll
        for (int nt = 0; nt < 4; nt++) {
            const int m = mBase + wr * 64 + mt * 16 + er;
            const int n = nBase + wc * 32 + nt * 8 + ec;
            const size_t g0 = (size_t)m * DD + n;
            const size_t g1 = g0 + 8 * DD;
            const float2 bz2 = *(const float2*)(&bz[n]);
            const float2 bh2 = *(const float2*)(&bh[n]);
            float2 av, bv;
            float z;
            z = sigmoidf_fast(accz[mt][nt][0] + bz2.x);
            av.x = 1.0f - z; bv.x = z * (acch[mt][nt][0] + bh2.x);
            z = sigmoidf_fast(accz[mt][nt][1] + bz2.y);
            av.y = 1.0f - z; bv.y = z * (acch[mt][nt][1] + bh2.y);
            *(float2*)(&g_a[g0]) = av;
            *(float2*)(&g_b[g0]) = bv;
            z = sigmoidf_fast(accz[mt][nt][2] + bz2.x);
            av.x = 1.0f - z; bv.x = z * (acch[mt][nt][2] + bh2.x);
            z = sigmoidf_fast(accz[mt][nt][3] + bz2.y);
            av.y = 1.0f - z; bv.y = z * (acch[mt][nt][3] + bh2.y);
            *(float2*)(&g_a[g1]) = av;
            *(float2*)(&g_b[g1]) = bv;
        }
    }
}

// ---------------- scan pass 1: per-chunk (A,B) summary, float4 ----------------
// thread handles 4 consecutive d for one (b,chunk). Layout g_Ac[bc][d].
__global__ __launch_bounds__(256)
void scan_pass1()
{
    const int g4 = blockIdx.x * 256 + threadIdx.x;   // (bc, d/4)
    const int bc = g4 >> 8;
    const int d0 = (g4 & 255) * 4;
    const size_t base = (size_t)bc * CHLEN * DD + d0;

    float4 Ar = make_float4(1.f, 1.f, 1.f, 1.f);
    float4 Br = make_float4(0.f, 0.f, 0.f, 0.f);
#pragma unroll 8
    for (int t = 0; t < CHLEN; t++) {
        const float4 av = *(const float4*)&g_a[base + (size_t)t * DD];
        const float4 bv = *(const float4*)&g_b[base + (size_t)t * DD];
        Br.x = fmaf(av.x, Br.x, bv.x); Ar.x *= av.x;
        Br.y = fmaf(av.y, Br.y, bv.y); Ar.y *= av.y;
        Br.z = fmaf(av.z, Br.z, bv.z); Ar.z *= av.z;
        Br.w = fmaf(av.w, Br.w, bv.w); Ar.w *= av.w;
    }
    *(float4*)&g_Ac[(size_t)bc * DD + d0] = Ar;
    *(float4*)&g_Bc[(size_t)bc * DD + d0] = Br;
}

// ---------------- fused: chunk-prefix + final scan + swish + LayerNorm -------
// CTA = one (b,chunk): 256 threads x 4 d. Per t: block-reduce mu/var, write out.
__global__ __launch_bounds__(256)
void scan_ln_kernel(const float* __restrict__ swish_beta,
                    const float* __restrict__ gamma,
                    const float* __restrict__ lbeta,
                    float* __restrict__ out)
{
    const int bc = blockIdx.x;            // b*NCHUNK + chunk
    const int b = bc >> 5;
    const int chunk = bc & 31;
    const int tid = threadIdx.x;
    const int lane = tid & 31;
    const int w = tid >> 5;
    const int d0 = tid * 4;
    const float beta = __ldg(swish_beta);

    // ---- hinit: prefix over predecessor chunk summaries ----
    float4 h = make_float4(0.f, 0.f, 0.f, 0.f);
    for (int c = 0; c < chunk; c++) {
        const size_t idx = (size_t)(b * NCHUNK + c) * DD + d0;
        const float4 A = *(const float4*)&g_Ac[idx];
        const float4 B = *(const float4*)&g_Bc[idx];
        h.x = fmaf(A.x, h.x, B.x);
        h.y = fmaf(A.y, h.y, B.y);
        h.z = fmaf(A.z, h.z, B.z);
        h.w = fmaf(A.w, h.w, B.w);
    }

    const float4 gm = *(const float4*)&gamma[d0];
    const float4 bt = *(const float4*)&lbeta[d0];

    __shared__ float sa[8], sb[8];
    __shared__ float s_mu, s_inv;

    const size_t base = (size_t)(b * TT + chunk * CHLEN) * DD + d0;
    float4 av = *(const float4*)&g_a[base];
    float4 bv = *(const float4*)&g_b[base];

    for (int t = 0; t < CHLEN; t++) {
        // recurrence + swish
        h.x = fmaf(av.x, h.x, bv.x);
        h.y = fmaf(av.y, h.y, bv.y);
        h.z = fmaf(av.z, h.z, bv.z);
        h.w = fmaf(av.w, h.w, bv.w);
        float4 y;
        {
            float s;
            s = beta * h.x; y.x = s * sigmoidf_fast(s);
            s = beta * h.y; y.y = s * sigmoidf_fast(s);
            s = beta * h.z; y.z = s * sigmoidf_fast(s);
            s = beta * h.w; y.w = s * sigmoidf_fast(s);
        }
        // prefetch t+1 before the reduction stalls
        if (t + 1 < CHLEN) {
            av = *(const float4*)&g_a[base + (size_t)(t + 1) * DD];
            bv = *(const float4*)&g_b[base + (size_t)(t + 1) * DD];
        }
        // block reduce sum / sumsq over 1024 d
        float s1 = y.x + y.y + y.z + y.w;
        float s2 = y.x * y.x + y.y * y.y + y.z * y.z + y.w * y.w;
#pragma unroll
        for (int o = 16; o > 0; o >>= 1) {
            s1 += __shfl_xor_sync(0xffffffffu, s1, o);
            s2 += __shfl_xor_sync(0xffffffffu, s2, o);
        }
        if (lane == 0) { sa[w] = s1; sb[w] = s2; }
        __syncthreads();
        if (tid < 32) {
            float a1 = (lane < 8) ? sa[lane] : 0.0f;
            float b1 = (lane < 8) ? sb[lane] : 0.0f;
#pragma unroll
            for (int o = 4; o > 0; o >>= 1) {
                a1 += __shfl_xor_sync(0xffffffffu, a1, o);
                b1 += __shfl_xor_sync(0xffffffffu, b1, o);
            }
            if (lane == 0) {
                const float mu  = a1 * (1.0f / DD);
                const float var = b1 * (1.0f / DD) - mu * mu;
                s_mu  = mu;
                s_inv = rsqrtf(var + 1e-5f);
            }
        }
        __syncthreads();
        const float mu  = s_mu;
        const float inv = s_inv;
        float4 o;
        o.x = (y.x - mu) * inv * gm.x + bt.x;
        o.y = (y.y - mu) * inv * gm.y + bt.y;
        o.z = (y.z - mu) * inv * gm.z + bt.z;
        o.w = (y.w - mu) * inv * gm.w + bt.w;
        *(float4*)&out[base + (size_t)t * DD] = o;
    }
}

// ---------------- launch ----------------
extern "C" void kernel_launch(void* const* d_in, const int* in_sizes, int n_in,
                              void* d_out, int out_size)
{
    const float* x     = (const float*)d_in[0];
    const float* Wz    = (const float*)d_in[1];
    const float* bz    = (const float*)d_in[2];
    const float* Wh    = (const float*)d_in[3];
    const float* bh    = (const float*)d_in[4];
    const float* sbeta = (const float*)d_in[5];
    const float* gamma = (const float*)d_in[6];
    const float* lbeta = (const float*)d_in[7];
    float* out = (float*)d_out;

    convert_x_kernel<<<(MM * DD) / (256 * 4), 256>>>(x);
    transpose_kernel<<<dim3(32, 32, 2), 256>>>(Wz, Wh);

    dim3 gemmGrid(DD / 128, MM / 128);   // (8, 128)
    cudaError_t e = cudaFuncSetAttribute(
        gemm_fused_kernel<4>, cudaFuncAttributeMaxDynamicSharedMemorySize,
        4 * STAGE_B);
    if (e == cudaSuccess) {
        gemm_fused_kernel<4><<<gemmGrid, 256, 4 * STAGE_B>>>(bz, bh);
    } else {
        (void)cudaGetLastError();   // clear; fall back to 48KB 2-stage
        gemm_fused_kernel<2><<<gemmGrid, 256, 2 * STAGE_B>>>(bz, bh);
    }

    scan_pass1<<<(BB * NCHUNK * DD) / (256 * 4), 256>>>();
    scan_ln_kernel<<<BB * NCHUNK, 256>>>(sbeta, gamma, lbeta, out);
}

// round 7
// speedup vs baseline: 1.0659x; 1.0659x over previous
#include <cuda_runtime.h>
#include <cuda_fp16.h>
#include <math.h>
#include <stdint.h>

// Problem shape (fixed): B=8, T=2048, D=1024
#define BB   8
#define TT   2048
#define DD   1024
#define MM   (BB*TT)          // 16384 rows
#define NCHUNK 32
#define CHLEN  64

// ---- BK=64 GEMM (primary): CTA 128x128, 2 outputs, warp 64x32x2 ----
#define NCH64   16
#define A64_OFF  0
#define BZ64_OFF 16384
#define BH64_OFF 32768
#define STAGE64  49152        // 48KB per stage; 2 stages = 96KB

// ---- BK=32 GEMM (fallback, 48KB default smem) ----
#define NCH32   32
#define A32_OFF  0
#define BZ32_OFF 8192
#define BH32_OFF 16384
#define STAGE32  24576

// ---------------- scratch (device globals) ----------------
__device__ float g_y[(size_t)MM * DD];
__device__ float g_a[(size_t)MM * DD];
__device__ float g_b[(size_t)MM * DD];
__device__ float g_Ac[BB * NCHUNK * DD];
__device__ float g_Bc[BB * NCHUNK * DD];

__device__ __half g_xh[(size_t)MM * DD];    // x in fp16
__device__ __half g_Wtz[DD * DD];           // Wz^T fp16: [n][k]
__device__ __half g_Wth[DD * DD];           // Wh^T fp16: [n][k]

__device__ __forceinline__ float sigmoidf_fast(float v) {
    return 1.0f / (1.0f + __expf(-v));
}

// ---------------- PTX helpers ----------------
__device__ __forceinline__ uint32_t smem_u32(const void* p) {
    uint32_t a;
    asm("{ .reg .u64 t; cvta.to.shared.u64 t, %1; cvt.u32.u64 %0, t; }" : "=r"(a) : "l"(p));
    return a;
}
#define SWZ64(o)  ((o) ^ (((o) >> 3) & 0x30))
#define SWZ128(o) ((o) ^ (((o) >> 3) & 0x70))

__device__ __forceinline__ void cp16(uint32_t s, const void* g) {
    asm volatile("cp.async.cg.shared.global [%0], [%1], 16;" :: "r"(s), "l"(g));
}
__device__ __forceinline__ void cp_commit() {
    asm volatile("cp.async.commit_group;" ::: "memory");
}
__device__ __forceinline__ void ldsm_x4(uint32_t& r0, uint32_t& r1, uint32_t& r2,
                                        uint32_t& r3, uint32_t addr) {
    asm volatile("ldmatrix.sync.aligned.m8n8.x4.shared.b16 {%0,%1,%2,%3}, [%4];"
                 : "=r"(r0), "=r"(r1), "=r"(r2), "=r"(r3) : "r"(addr));
}
__device__ __forceinline__ void mma_f16(float* d, const uint32_t* a, const uint32_t* b) {
    asm volatile(
        "mma.sync.aligned.m16n8k16.row.col.f32.f16.f16.f32 "
        "{%0,%1,%2,%3},{%4,%5,%6,%7},{%8,%9},{%0,%1,%2,%3};"
        : "+f"(d[0]), "+f"(d[1]), "+f"(d[2]), "+f"(d[3])
        : "r"(a[0]), "r"(a[1]), "r"(a[2]), "r"(a[3]), "r"(b[0]), "r"(b[1]));
}

// ---------------- prep: convert x to fp16 ----------------
__global__ __launch_bounds__(256)
void convert_x_kernel(const float* __restrict__ x)
{
    const size_t i4 = (size_t)blockIdx.x * 256 + threadIdx.x;
    const float4 v = ((const float4*)x)[i4];
    __half2 p0, p1;
    p0.x = __float2half_rn(v.x); p0.y = __float2half_rn(v.y);
    p1.x = __float2half_rn(v.z); p1.y = __float2half_rn(v.w);
    ((__half2*)g_xh)[i4 * 2]     = p0;
    ((__half2*)g_xh)[i4 * 2 + 1] = p1;
}

// ---------------- prep: transpose W -> Wt[n][k], fp16 ----------------
__global__ __launch_bounds__(256)
void transpose_kernel(const float* __restrict__ Wz, const float* __restrict__ Wh)
{
    __shared__ float sm[32][33];
    const float* W = (blockIdx.z == 0) ? Wz : Wh;
    __half* Wt = (blockIdx.z == 0) ? g_Wtz : g_Wth;

    const int k0 = blockIdx.y * 32;
    const int n0 = blockIdx.x * 32;
    const int r = threadIdx.x >> 5;
    const int c = threadIdx.x & 31;
#pragma unroll
    for (int rr = 0; rr < 4; rr++) {
        const int row = rr * 8 + r;
        sm[row][c] = W[(size_t)(k0 + row) * DD + n0 + c];
    }
    __syncthreads();
#pragma unroll
    for (int rr = 0; rr < 4; rr++) {
        const int row = rr * 8 + r;
        Wt[(size_t)(n0 + row) * DD + k0 + c] = __float2half_rn(sm[c][row]);
    }
}

// ---------------- shared epilogue: a = 1-z, b = z*(hlin+bh) ----------------
__device__ __forceinline__ void gemm_epilogue(
    float accz[4][4][4], float acch[4][4][4],
    const float* __restrict__ bz, const float* __restrict__ bh,
    int mBase, int nBase, int wr, int wc, int lane)
{
    const int er = lane >> 2;
    const int ec = (lane & 3) * 2;
#pragma unroll
    for (int mt = 0; mt < 4; mt++) {
#pragma unroll
        for (int nt = 0; nt < 4; nt++) {
            const int m = mBase + wr * 64 + mt * 16 + er;
            const int n = nBase + wc * 32 + nt * 8 + ec;
            const size_t g0 = (size_t)m * DD + n;
            const size_t g1 = g0 + 8 * DD;
            const float2 bz2 = *(const float2*)(&bz[n]);
            const float2 bh2 = *(const float2*)(&bh[n]);
            float2 av, bv;
            float z;
            z = sigmoidf_fast(accz[mt][nt][0] + bz2.x);
            av.x = 1.0f - z; bv.x = z * (acch[mt][nt][0] + bh2.x);
            z = sigmoidf_fast(accz[mt][nt][1] + bz2.y);
            av.y = 1.0f - z; bv.y = z * (acch[mt][nt][1] + bh2.y);
            *(float2*)(&g_a[g0]) = av;
            *(float2*)(&g_b[g0]) = bv;
            z = sigmoidf_fast(accz[mt][nt][2] + bz2.x);
            av.x = 1.0f - z; bv.x = z * (acch[mt][nt][2] + bh2.x);
            z = sigmoidf_fast(accz[mt][nt][3] + bz2.y);
            av.y = 1.0f - z; bv.y = z * (acch[mt][nt][3] + bh2.y);
            *(float2*)(&g_a[g1]) = av;
            *(float2*)(&g_b[g1]) = bv;
        }
    }
}

// ---------------- PRIMARY GEMM: BK=64, 2-stage, 96KB smem --------------------
__global__ __launch_bounds__(256, 1)
void gemm64_kernel(const float* __restrict__ bz, const float* __restrict__ bh)
{
    extern __shared__ char smem[];
    const uint32_t sbase = smem_u32(smem);
    const int tid  = threadIdx.x;
    const int wid  = tid >> 5;
    const int lane = tid & 31;
    const int wr = wid >> 2;
    const int wc = wid & 3;

    const int nBase = blockIdx.x * 128;
    const int mBase = blockIdx.y * 128;

    // ---- cp.async static addressing: per region, 4x 16B per thread (128B rows)
    int ldRow[4];
    int ldCol[4];
    uint32_t ldOff[4];
#pragma unroll
    for (int t = 0; t < 4; t++) {
        const int o = tid + t * 256;
        ldRow[t] = o >> 3;             // 128 rows x 8 chunks of 16B
        ldCol[t] = o & 7;
        ldOff[t] = SWZ128((uint32_t)(o * 16));
    }

    // ---- ldmatrix static offsets (128B rows, 4 k-steps) ----
    const int quad = lane >> 3;
    const int r8   = lane & 7;
    const int rowA = (quad & 1) * 8 + r8;
    const int kbA  = (quad >> 1) * 16;
    const int rowB = (quad >> 1) * 8 + r8;
    const int kbB  = (quad & 1) * 16;

    uint32_t offA[4][4], offB[4][2];
#pragma unroll
    for (int ks = 0; ks < 4; ks++) {
#pragma unroll
        for (int mt = 0; mt < 4; mt++)
            offA[ks][mt] = SWZ128((uint32_t)((wr * 64 + mt * 16 + rowA) * 128 + ks * 32 + kbA));
#pragma unroll
        for (int bt = 0; bt < 2; bt++)
            offB[ks][bt] = SWZ128((uint32_t)((wc * 32 + bt * 16 + rowB) * 128 + ks * 32 + kbB));
    }

    float accz[4][4][4], acch[4][4][4];
#pragma unroll
    for (int i = 0; i < 4; i++)
#pragma unroll
        for (int j = 0; j < 4; j++)
#pragma unroll
            for (int k = 0; k < 4; k++) { accz[i][j][k] = 0.0f; acch[i][j][k] = 0.0f; }

    auto load_chunk = [&](int chunk, int stage) {
        const int k0 = chunk * 64;
        const uint32_t st = sbase + stage * STAGE64;
#pragma unroll
        for (int t = 0; t < 4; t++) {
            const size_t rowOff = (size_t)ldRow[t] * DD + k0 + ldCol[t] * 8;
            cp16(st + A64_OFF  + ldOff[t], g_xh  + (size_t)mBase * DD + rowOff);
            cp16(st + BZ64_OFF + ldOff[t], g_Wtz + (size_t)nBase * DD + rowOff);
            cp16(st + BH64_OFF + ldOff[t], g_Wth + (size_t)nBase * DD + rowOff);
        }
        cp_commit();
    };

    load_chunk(0, 0);

    for (int i = 0; i < NCH64; i++) {
        const int s = i & 1;
        asm volatile("cp.async.wait_group 0;" ::: "memory");
        __syncthreads();
        if (i + 1 < NCH64) load_chunk(i + 1, s ^ 1);

        const uint32_t st = sbase + s * STAGE64;
#pragma unroll
        for (int ks = 0; ks < 4; ks++) {
            uint32_t af[4][4];
#pragma unroll
            for (int mt = 0; mt < 4; mt++)
                ldsm_x4(af[mt][0], af[mt][1], af[mt][2], af[mt][3],
                        st + A64_OFF + offA[ks][mt]);
            {
                uint32_t bf[4][2];
#pragma unroll
                for (int bt = 0; bt < 2; bt++)
                    ldsm_x4(bf[bt*2][0], bf[bt*2][1], bf[bt*2+1][0], bf[bt*2+1][1],
                            st + BZ64_OFF + offB[ks][bt]);
#pragma unroll
                for (int mt = 0; mt < 4; mt++)
#pragma unroll
                    for (int nt = 0; nt < 4; nt++)
                        mma_f16(accz[mt][nt], af[mt], bf[nt]);
            }
            {
                uint32_t bf[4][2];
#pragma unroll
                for (int bt = 0; bt < 2; bt++)
                    ldsm_x4(bf[bt*2][0], bf[bt*2][1], bf[bt*2+1][0], bf[bt*2+1][1],
                            st + BH64_OFF + offB[ks][bt]);
#pragma unroll
                for (int mt = 0; mt < 4; mt++)
#pragma unroll
                    for (int nt = 0; nt < 4; nt++)
                        mma_f16(acch[mt][nt], af[mt], bf[nt]);
            }
        }
    }

    gemm_epilogue(accz, acch, bz, bh, mBase, nBase, wr, wc, lane);
}

// ---------------- FALLBACK GEMM: BK=32, 2-stage, 48KB (proven R5) ------------
__global__ __launch_bounds__(256, 1)
void gemm32_kernel(const float* __restrict__ bz, const float* __restrict__ bh)
{
    extern __shared__ char smem[];
    const uint32_t sbase = smem_u32(smem);
    const int tid  = threadIdx.x;
    const int wid  = tid >> 5;
    const int lane = tid & 31;
    const int wr = wid >> 2;
    const int wc = wid & 3;

    const int nBase = blockIdx.x * 128;
    const int mBase = blockIdx.y * 128;

    int ldRow[2];
    int ldCol[2];
    uint32_t ldOff[2];
#pragma unroll
    for (int t = 0; t < 2; t++) {
        const int o = tid + t * 256;
        ldRow[t] = o >> 2;
        ldCol[t] = o & 3;
        ldOff[t] = SWZ64((uint32_t)(o * 16));
    }

    const int quad = lane >> 3;
    const int r8   = lane & 7;
    const int rowA = (quad & 1) * 8 + r8;
    const int kbA  = (quad >> 1) * 16;
    const int rowB = (quad >> 1) * 8 + r8;
    const int kbB  = (quad & 1) * 16;

    uint32_t offA[2][4], offB[2][2];
#pragma unroll
    for (int ks = 0; ks < 2; ks++) {
#pragma unroll
        for (int mt = 0; mt < 4; mt++)
            offA[ks][mt] = SWZ64((uint32_t)((wr * 64 + mt * 16 + rowA) * 64 + ks * 32 + kbA));
#pragma unroll
        for (int bt = 0; bt < 2; bt++)
            offB[ks][bt] = SWZ64((uint32_t)((wc * 32 + bt * 16 + rowB) * 64 + ks * 32 + kbB));
    }

    float accz[4][4][4], acch[4][4][4];
#pragma unroll
    for (int i = 0; i < 4; i++)
#pragma unroll
        for (int j = 0; j < 4; j++)
#pragma unroll
            for (int k = 0; k < 4; k++) { accz[i][j][k] = 0.0f; acch[i][j][k] = 0.0f; }

    auto load_chunk = [&](int chunk, int stage) {
        const int k0 = chunk * 32;
        const uint32_t st = sbase + stage * STAGE32;
#pragma unroll
        for (int t = 0; t < 2; t++) {
            const size_t rowOff = (size_t)ldRow[t] * DD + k0 + ldCol[t] * 8;
            cp16(st + A32_OFF  + ldOff[t], g_xh  + (size_t)mBase * DD + rowOff);
            cp16(st + BZ32_OFF + ldOff[t], g_Wtz + (size_t)nBase * DD + rowOff);
            cp16(st + BH32_OFF + ldOff[t], g_Wth + (size_t)nBase * DD + rowOff);
        }
        cp_commit();
    };

    load_chunk(0, 0);

    for (int i = 0; i < NCH32; i++) {
        const int s = i & 1;
        asm volatile("cp.async.wait_group 0;" ::: "memory");
        __syncthreads();
        if (i + 1 < NCH32) load_chunk(i + 1, s ^ 1);

        const uint32_t st = sbase + s * STAGE32;
#pragma unroll
        for (int ks = 0; ks < 2; ks++) {
            uint32_t af[4][4];
#pragma unroll
            for (int mt = 0; mt < 4; mt++)
                ldsm_x4(af[mt][0], af[mt][1], af[mt][2], af[mt][3],
                        st + A32_OFF + offA[ks][mt]);
            {
                uint32_t bf[4][2];
#pragma unroll
                for (int bt = 0; bt < 2; bt++)
                    ldsm_x4(bf[bt*2][0], bf[bt*2][1], bf[bt*2+1][0], bf[bt*2+1][1],
                            st + BZ32_OFF + offB[ks][bt]);
#pragma unroll
                for (int mt = 0; mt < 4; mt++)
#pragma unroll
                    for (int nt = 0; nt < 4; nt++)
                        mma_f16(accz[mt][nt], af[mt], bf[nt]);
            }
            {
                uint32_t bf[4][2];
#pragma unroll
                for (int bt = 0; bt < 2; bt++)
                    ldsm_x4(bf[bt*2][0], bf[bt*2][1], bf[bt*2+1][0], bf[bt*2+1][1],
                            st + BH32_OFF + offB[ks][bt]);
#pragma unroll
                for (int mt = 0; mt < 4; mt++)
#pragma unroll
                    for (int nt = 0; nt < 4; nt++)
                        mma_f16(acch[mt][nt], af[mt], bf[nt]);
            }
        }
    }

    gemm_epilogue(accz, acch, bz, bh, mBase, nBase, wr, wc, lane);
}

// ---------------- scan pass 1: per-chunk (A,B) summary, float2 ----------------
__global__ __launch_bounds__(256)
void scan_pass1()
{
    const int g2 = blockIdx.x * 256 + threadIdx.x;   // (bc, d/2)
    const int bc = g2 >> 9;
    const int d0 = (g2 & 511) * 2;
    const size_t base = (size_t)bc * CHLEN * DD + d0;

    float2 Ar = make_float2(1.f, 1.f);
    float2 Br = make_float2(0.f, 0.f);
#pragma unroll 8
    for (int t = 0; t < CHLEN; t++) {
        const float2 av = *(const float2*)&g_a[base + (size_t)t * DD];
        const float2 bv = *(const float2*)&g_b[base + (size_t)t * DD];
        Br.x = fmaf(av.x, Br.x, bv.x); Ar.x *= av.x;
        Br.y = fmaf(av.y, Br.y, bv.y); Ar.y *= av.y;
    }
    *(float2*)&g_Ac[(size_t)bc * DD + d0] = Ar;
    *(float2*)&g_Bc[(size_t)bc * DD + d0] = Br;
}

// ---------------- fused: chunk-prefix + scan + swish + LayerNorm -------------
// Phase A: recurrence+swish for 64 t, y -> gmem, per-(t,warp) sums -> smem
//          (no barriers). Phase B: finalize mu/inv (2 barriers), normalize.
__global__ __launch_bounds__(256)
void scan_ln_kernel(const float* __restrict__ swish_beta,
                    const float* __restrict__ gamma,
                    const float* __restrict__ lbeta,
                    float* __restrict__ out)
{
    const int bc = blockIdx.x;            // b*NCHUNK + chunk
    const int b = bc >> 5;
    const int chunk = bc & 31;
    const int tid = threadIdx.x;
    const int lane = tid & 31;
    const int w = tid >> 5;
    const int d0 = tid * 4;
    const float beta = __ldg(swish_beta);

    __shared__ float s1s[CHLEN][9], s2s[CHLEN][9];
    __shared__ float smu[CHLEN], sinv[CHLEN];

    // ---- hinit: prefix over predecessor chunk summaries ----
    float4 h = make_float4(0.f, 0.f, 0.f, 0.f);
    for (int c = 0; c < chunk; c++) {
        const size_t idx = (size_t)(b * NCHUNK + c) * DD + d0;
        const float4 A = *(const float4*)&g_Ac[idx];
        const float4 B = *(const float4*)&g_Bc[idx];
        h.x = fmaf(A.x, h.x, B.x);
        h.y = fmaf(A.y, h.y, B.y);
        h.z = fmaf(A.z, h.z, B.z);
        h.w = fmaf(A.w, h.w, B.w);
    }

    const size_t base = (size_t)(b * TT + chunk * CHLEN) * DD + d0;
    float4 av = *(const float4*)&g_a[base];
    float4 bv = *(const float4*)&g_b[base];

    // ---- Phase A ----
    for (int t = 0; t < CHLEN; t++) {
        h.x = fmaf(av.x, h.x, bv.x);
        h.y = fmaf(av.y, h.y, bv.y);
        h.z = fmaf(av.z, h.z, bv.z);
        h.w = fmaf(av.w, h.w, bv.w);
        float4 y;
        {
            float s;
            s = beta * h.x; y.x = s * sigmoidf_fast(s);
            s = beta * h.y; y.y = s * sigmoidf_fast(s);
            s = beta * h.z; y.z = s * sigmoidf_fast(s);
            s = beta * h.w; y.w = s * sigmoidf_fast(s);
        }
        if (t + 1 < CHLEN) {
            av = *(const float4*)&g_a[base + (size_t)(t + 1) * DD];
            bv = *(const float4*)&g_b[base + (size_t)(t + 1) * DD];
        }
        *(float4*)&g_y[base + (size_t)t * DD] = y;

        float s1 = y.x + y.y + y.z + y.w;
        float s2 = y.x * y.x + y.y * y.y + y.z * y.z + y.w * y.w;
#pragma unroll
        for (int o = 16; o > 0; o >>= 1) {
            s1 += __shfl_xor_sync(0xffffffffu, s1, o);
            s2 += __shfl_xor_sync(0xffffffffu, s2, o);
        }
        if (lane == 0) { s1s[t][w] = s1; s2s[t][w] = s2; }
    }
    __syncthreads();

    // finalize mu / inv per timestep (threads 0..63)
    if (tid < CHLEN) {
        float a1 = 0.0f, b1 = 0.0f;
#pragma unroll
        for (int j = 0; j < 8; j++) { a1 += s1s[tid][j]; b1 += s2s[tid][j]; }
        const float mu  = a1 * (1.0f / DD);
        const float var = b1 * (1.0f / DD) - mu * mu;
        smu[tid]  = mu;
        sinv[tid] = rsqrtf(var + 1e-5f);
    }
    __syncthreads();

    // ---- Phase B: normalize (y re-read is L2-resident) ----
    const float4 gm = *(const float4*)&gamma[d0];
    const float4 bt = *(const float4*)&lbeta[d0];
#pragma unroll 4
    for (int t = 0; t < CHLEN; t++) {
        const float4 y = *(const float4*)&g_y[base + (size_t)t * DD];
        const float mu  = smu[t];
        const float inv = sinv[t];
        float4 o;
        o.x = (y.x - mu) * inv * gm.x + bt.x;
        o.y = (y.y - mu) * inv * gm.y + bt.y;
        o.z = (y.z - mu) * inv * gm.z + bt.z;
        o.w = (y.w - mu) * inv * gm.w + bt.w;
        *(float4*)&out[base + (size_t)t * DD] = o;
    }
}

// ---------------- launch ----------------
extern "C" void kernel_launch(void* const* d_in, const int* in_sizes, int n_in,
                              void* d_out, int out_size)
{
    const float* x     = (const float*)d_in[0];
    const float* Wz    = (const float*)d_in[1];
    const float* bz    = (const float*)d_in[2];
    const float* Wh    = (const float*)d_in[3];
    const float* bh    = (const float*)d_in[4];
    const float* sbeta = (const float*)d_in[5];
    const float* gamma = (const float*)d_in[6];
    const float* lbeta = (const float*)d_in[7];
    float* out = (float*)d_out;

    convert_x_kernel<<<(MM * DD) / (256 * 4), 256>>>(x);
    transpose_kernel<<<dim3(32, 32, 2), 256>>>(Wz, Wh);

    dim3 gemmGrid(DD / 128, MM / 128);   // (8, 128)
    cudaError_t e = cudaFuncSetAttribute(
        gemm64_kernel, cudaFuncAttributeMaxDynamicSharedMemorySize, 2 * STAGE64);
    if (e == cudaSuccess) {
        gemm64_kernel<<<gemmGrid, 256, 2 * STAGE64>>>(bz, bh);
    } else {
        (void)cudaGetLastError();
        gemm32_kernel<<<gemmGrid, 256, 2 * STAGE32>>>(bz, bh);
    }

    scan_pass1<<<(BB * NCHUNK * DD) / (256 * 2), 256>>>();
    scan_ln_kernel<<<BB * NCHUNK, 256>>>(sbeta, gamma, lbeta, out);
}

// round 9
// speedup vs baseline: 1.1887x; 1.1152x over previous
#include <cuda_runtime.h>
#include <cuda_fp16.h>
#include <math.h>
#include <stdint.h>

// Problem shape (fixed): B=8, T=2048, D=1024
#define BB   8
#define TT   2048
#define DD   1024
#define MM   (BB*TT)          // 16384 rows
#define NCHUNK 32
#define CHLEN  64

// ---- BK=64 GEMM (primary): CTA 128x128, 2 outputs, warp 64x32x2 ----
#define NCH64   16
#define A64_OFF  0
#define BZ64_OFF 16384
#define BH64_OFF 32768
#define STAGE64  49152        // 48KB per stage; 2 stages = 96KB

// ---- BK=32 GEMM (fallback, 48KB default smem) ----
#define NCH32   32
#define A32_OFF  0
#define BZ32_OFF 8192
#define BH32_OFF 16384
#define STAGE32  24576

// ---------------- scratch (device globals) ----------------
__device__ __half2 g_ab[(size_t)MM * DD];   // {a, b} per element (fp16)
__device__ __half  g_y16[(size_t)MM * DD];  // swish output (fp16)
__device__ float   g_Ac[BB * NCHUNK * DD];  // chunk summaries (fp32)
__device__ float   g_Bc[BB * NCHUNK * DD];

__device__ __half g_xh[(size_t)MM * DD];    // x in fp16
__device__ __half g_Wtz[DD * DD];           // Wz^T fp16: [n][k]
__device__ __half g_Wth[DD * DD];           // Wh^T fp16: [n][k]

__device__ __forceinline__ float sigmoidf_fast(float v) {
    return 1.0f / (1.0f + __expf(-v));
}

// ---- bit casts (these intrinsics don't exist; do it manually) ----
__device__ __forceinline__ uint32_t h2_to_u32(__half2 h) {
    return *reinterpret_cast<uint32_t*>(&h);
}
__device__ __forceinline__ __half2 u32_to_h2(uint32_t u) {
    return *reinterpret_cast<__half2*>(&u);
}

// ---------------- PTX helpers ----------------
__device__ __forceinline__ uint32_t smem_u32(const void* p) {
    uint32_t a;
    asm("{ .reg .u64 t; cvta.to.shared.u64 t, %1; cvt.u32.u64 %0, t; }" : "=r"(a) : "l"(p));
    return a;
}
#define SWZ64(o)  ((o) ^ (((o) >> 3) & 0x30))
#define SWZ128(o) ((o) ^ (((o) >> 3) & 0x70))

__device__ __forceinline__ void cp16(uint32_t s, const void* g) {
    asm volatile("cp.async.cg.shared.global [%0], [%1], 16;" :: "r"(s), "l"(g));
}
__device__ __forceinline__ void cp_commit() {
    asm volatile("cp.async.commit_group;" ::: "memory");
}
__device__ __forceinline__ void ldsm_x4(uint32_t& r0, uint32_t& r1, uint32_t& r2,
                                        uint32_t& r3, uint32_t addr) {
    asm volatile("ldmatrix.sync.aligned.m8n8.x4.shared.b16 {%0,%1,%2,%3}, [%4];"
                 : "=r"(r0), "=r"(r1), "=r"(r2), "=r"(r3) : "r"(addr));
}
__device__ __forceinline__ void mma_f16(float* d, const uint32_t* a, const uint32_t* b) {
    asm volatile(
        "mma.sync.aligned.m16n8k16.row.col.f32.f16.f16.f32 "
        "{%0,%1,%2,%3},{%4,%5,%6,%7},{%8,%9},{%0,%1,%2,%3};"
        : "+f"(d[0]), "+f"(d[1]), "+f"(d[2]), "+f"(d[3])
        : "r"(a[0]), "r"(a[1]), "r"(a[2]), "r"(a[3]), "r"(b[0]), "r"(b[1]));
}

// ---------------- prep: convert x to fp16 ----------------
__global__ __launch_bounds__(256)
void convert_x_kernel(const float* __restrict__ x)
{
    const size_t i4 = (size_t)blockIdx.x * 256 + threadIdx.x;
    const float4 v = ((const float4*)x)[i4];
    __half2 p0, p1;
    p0.x = __float2half_rn(v.x); p0.y = __float2half_rn(v.y);
    p1.x = __float2half_rn(v.z); p1.y = __float2half_rn(v.w);
    ((__half2*)g_xh)[i4 * 2]     = p0;
    ((__half2*)g_xh)[i4 * 2 + 1] = p1;
}

// ---------------- prep: transpose W -> Wt[n][k], fp16 ----------------
__global__ __launch_bounds__(256)
void transpose_kernel(const float* __restrict__ Wz, const float* __restrict__ Wh)
{
    __shared__ float sm[32][33];
    const float* W = (blockIdx.z == 0) ? Wz : Wh;
    __half* Wt = (blockIdx.z == 0) ? g_Wtz : g_Wth;

    const int k0 = blockIdx.y * 32;
    const int n0 = blockIdx.x * 32;
    const int r = threadIdx.x >> 5;
    const int c = threadIdx.x & 31;
#pragma unroll
    for (int rr = 0; rr < 4; rr++) {
        const int row = rr * 8 + r;
        sm[row][c] = W[(size_t)(k0 + row) * DD + n0 + c];
    }
    __syncthreads();
#pragma unroll
    for (int rr = 0; rr < 4; rr++) {
        const int row = rr * 8 + r;
        Wt[(size_t)(n0 + row) * DD + k0 + c] = __float2half_rn(sm[c][row]);
    }
}

// ---------------- shared epilogue: {a,b} fp16 interleaved ----------------
__device__ __forceinline__ void gemm_epilogue(
    float accz[4][4][4], float acch[4][4][4],
    const float* __restrict__ bz, const float* __restrict__ bh,
    int mBase, int nBase, int wr, int wc, int lane)
{
    const int er = lane >> 2;
    const int ec = (lane & 3) * 2;
#pragma unroll
    for (int mt = 0; mt < 4; mt++) {
#pragma unroll
        for (int nt = 0; nt < 4; nt++) {
            const int m = mBase + wr * 64 + mt * 16 + er;
            const int n = nBase + wc * 32 + nt * 8 + ec;
            const size_t g0 = (size_t)m * DD + n;
            const size_t g1 = g0 + 8 * DD;
            const float2 bz2 = *(const float2*)(&bz[n]);
            const float2 bh2 = *(const float2*)(&bh[n]);
            float z;
            __half2 p0, p1;
            z = sigmoidf_fast(accz[mt][nt][0] + bz2.x);
            p0.x = __float2half_rn(1.0f - z);
            p0.y = __float2half_rn(z * (acch[mt][nt][0] + bh2.x));
            z = sigmoidf_fast(accz[mt][nt][1] + bz2.y);
            p1.x = __float2half_rn(1.0f - z);
            p1.y = __float2half_rn(z * (acch[mt][nt][1] + bh2.y));
            *(uint2*)(&g_ab[g0]) = make_uint2(h2_to_u32(p0), h2_to_u32(p1));
            z = sigmoidf_fast(accz[mt][nt][2] + bz2.x);
            p0.x = __float2half_rn(1.0f - z);
            p0.y = __float2half_rn(z * (acch[mt][nt][2] + bh2.x));
            z = sigmoidf_fast(accz[mt][nt][3] + bz2.y);
            p1.x = __float2half_rn(1.0f - z);
            p1.y = __float2half_rn(z * (acch[mt][nt][3] + bh2.y));
            *(uint2*)(&g_ab[g1]) = make_uint2(h2_to_u32(p0), h2_to_u32(p1));
        }
    }
}

// ---------------- PRIMARY GEMM: BK=64, 2-stage, 96KB smem --------------------
__global__ __launch_bounds__(256, 1)
void gemm64_kernel(const float* __restrict__ bz, const float* __restrict__ bh)
{
    extern __shared__ char smem[];
    const uint32_t sbase = smem_u32(smem);
    const int tid  = threadIdx.x;
    const int wid  = tid >> 5;
    const int lane = tid & 31;
    const int wr = wid >> 2;
    const int wc = wid & 3;

    const int nBase = blockIdx.x * 128;
    const int mBase = blockIdx.y * 128;

    int ldRow[4];
    int ldCol[4];
    uint32_t ldOff[4];
#pragma unroll
    for (int t = 0; t < 4; t++) {
        const int o = tid + t * 256;
        ldRow[t] = o >> 3;
        ldCol[t] = o & 7;
        ldOff[t] = SWZ128((uint32_t)(o * 16));
    }

    const int quad = lane >> 3;
    const int r8   = lane & 7;
    const int rowA = (quad & 1) * 8 + r8;
    const int kbA  = (quad >> 1) * 16;
    const int rowB = (quad >> 1) * 8 + r8;
    const int kbB  = (quad & 1) * 16;

    uint32_t offA[4][4], offB[4][2];
#pragma unroll
    for (int ks = 0; ks < 4; ks++) {
#pragma unroll
        for (int mt = 0; mt < 4; mt++)
            offA[ks][mt] = SWZ128((uint32_t)((wr * 64 + mt * 16 + rowA) * 128 + ks * 32 + kbA));
#pragma unroll
        for (int bt = 0; bt < 2; bt++)
            offB[ks][bt] = SWZ128((uint32_t)((wc * 32 + bt * 16 + rowB) * 128 + ks * 32 + kbB));
    }

    float accz[4][4][4], acch[4][4][4];
#pragma unroll
    for (int i = 0; i < 4; i++)
#pragma unroll
        for (int j = 0; j < 4; j++)
#pragma unroll
            for (int k = 0; k < 4; k++) { accz[i][j][k] = 0.0f; acch[i][j][k] = 0.0f; }

    auto load_chunk = [&](int chunk, int stage) {
        const int k0 = chunk * 64;
        const uint32_t st = sbase + stage * STAGE64;
#pragma unroll
        for (int t = 0; t < 4; t++) {
            const size_t rowOff = (size_t)ldRow[t] * DD + k0 + ldCol[t] * 8;
            cp16(st + A64_OFF  + ldOff[t], g_xh  + (size_t)mBase * DD + rowOff);
            cp16(st + BZ64_OFF + ldOff[t], g_Wtz + (size_t)nBase * DD + rowOff);
            cp16(st + BH64_OFF + ldOff[t], g_Wth + (size_t)nBase * DD + rowOff);
        }
        cp_commit();
    };

    load_chunk(0, 0);

    for (int i = 0; i < NCH64; i++) {
        const int s = i & 1;
        asm volatile("cp.async.wait_group 0;" ::: "memory");
        __syncthreads();
        if (i + 1 < NCH64) load_chunk(i + 1, s ^ 1);

        const uint32_t st = sbase + s * STAGE64;
#pragma unroll
        for (int ks = 0; ks < 4; ks++) {
            uint32_t af[4][4];
#pragma unroll
            for (int mt = 0; mt < 4; mt++)
                ldsm_x4(af[mt][0], af[mt][1], af[mt][2], af[mt][3],
                        st + A64_OFF + offA[ks][mt]);
            {
                uint32_t bf[4][2];
#pragma unroll
                for (int bt = 0; bt < 2; bt++)
                    ldsm_x4(bf[bt*2][0], bf[bt*2][1], bf[bt*2+1][0], bf[bt*2+1][1],
                            st + BZ64_OFF + offB[ks][bt]);
#pragma unroll
                for (int mt = 0; mt < 4; mt++)
#pragma unroll
                    for (int nt = 0; nt < 4; nt++)
                        mma_f16(accz[mt][nt], af[mt], bf[nt]);
            }
            {
                uint32_t bf[4][2];
#pragma unroll
                for (int bt = 0; bt < 2; bt++)
                    ldsm_x4(bf[bt*2][0], bf[bt*2][1], bf[bt*2+1][0], bf[bt*2+1][1],
                            st + BH64_OFF + offB[ks][bt]);
#pragma unroll
                for (int mt = 0; mt < 4; mt++)
#pragma unroll
                    for (int nt = 0; nt < 4; nt++)
                        mma_f16(acch[mt][nt], af[mt], bf[nt]);
            }
        }
    }

    gemm_epilogue(accz, acch, bz, bh, mBase, nBase, wr, wc, lane);
}

// ---------------- FALLBACK GEMM: BK=32, 2-stage, 48KB ------------
__global__ __launch_bounds__(256, 1)
void gemm32_kernel(const float* __restrict__ bz, const float* __restrict__ bh)
{
    extern __shared__ char smem[];
    const uint32_t sbase = smem_u32(smem);
    const int tid  = threadIdx.x;
    const int wid  = tid >> 5;
    const int lane = tid & 31;
    const int wr = wid >> 2;
    const int wc = wid & 3;

    const int nBase = blockIdx.x * 128;
    const int mBase = blockIdx.y * 128;

    int ldRow[2];
    int ldCol[2];
    uint32_t ldOff[2];
#pragma unroll
    for (int t = 0; t < 2; t++) {
        const int o = tid + t * 256;
        ldRow[t] = o >> 2;
        ldCol[t] = o & 3;
        ldOff[t] = SWZ64((uint32_t)(o * 16));
    }

    const int quad = lane >> 3;
    const int r8   = lane & 7;
    const int rowA = (quad & 1) * 8 + r8;
    const int kbA  = (quad >> 1) * 16;
    const int rowB = (quad >> 1) * 8 + r8;
    const int kbB  = (quad & 1) * 16;

    uint32_t offA[2][4], offB[2][2];
#pragma unroll
    for (int ks = 0; ks < 2; ks++) {
#pragma unroll
        for (int mt = 0; mt < 4; mt++)
            offA[ks][mt] = SWZ64((uint32_t)((wr * 64 + mt * 16 + rowA) * 64 + ks * 32 + kbA));
#pragma unroll
        for (int bt = 0; bt < 2; bt++)
            offB[ks][bt] = SWZ64((uint32_t)((wc * 32 + bt * 16 + rowB) * 64 + ks * 32 + kbB));
    }

    float accz[4][4][4], acch[4][4][4];
#pragma unroll
    for (int i = 0; i < 4; i++)
#pragma unroll
        for (int j = 0; j < 4; j++)
#pragma unroll
            for (int k = 0; k < 4; k++) { accz[i][j][k] = 0.0f; acch[i][j][k] = 0.0f; }

    auto load_chunk = [&](int chunk, int stage) {
        const int k0 = chunk * 32;
        const uint32_t st = sbase + stage * STAGE32;
#pragma unroll
        for (int t = 0; t < 2; t++) {
            const size_t rowOff = (size_t)ldRow[t] * DD + k0 + ldCol[t] * 8;
            cp16(st + A32_OFF  + ldOff[t], g_xh  + (size_t)mBase * DD + rowOff);
            cp16(st + BZ32_OFF + ldOff[t], g_Wtz + (size_t)nBase * DD + rowOff);
            cp16(st + BH32_OFF + ldOff[t], g_Wth + (size_t)nBase * DD + rowOff);
        }
        cp_commit();
    };

    load_chunk(0, 0);

    for (int i = 0; i < NCH32; i++) {
        const int s = i & 1;
        asm volatile("cp.async.wait_group 0;" ::: "memory");
        __syncthreads();
        if (i + 1 < NCH32) load_chunk(i + 1, s ^ 1);

        const uint32_t st = sbase + s * STAGE32;
#pragma unroll
        for (int ks = 0; ks < 2; ks++) {
            uint32_t af[4][4];
#pragma unroll
            for (int mt = 0; mt < 4; mt++)
                ldsm_x4(af[mt][0], af[mt][1], af[mt][2], af[mt][3],
                        st + A32_OFF + offA[ks][mt]);
            {
                uint32_t bf[4][2];
#pragma unroll
                for (int bt = 0; bt < 2; bt++)
                    ldsm_x4(bf[bt*2][0], bf[bt*2][1], bf[bt*2+1][0], bf[bt*2+1][1],
                            st + BZ32_OFF + offB[ks][bt]);
#pragma unroll
                for (int mt = 0; mt < 4; mt++)
#pragma unroll
                    for (int nt = 0; nt < 4; nt++)
                        mma_f16(accz[mt][nt], af[mt], bf[nt]);
            }
            {
                uint32_t bf[4][2];
#pragma unroll
                for (int bt = 0; bt < 2; bt++)
                    ldsm_x4(bf[bt*2][0], bf[bt*2][1], bf[bt*2+1][0], bf[bt*2+1][1],
                            st + BH32_OFF + offB[ks][bt]);
#pragma unroll
                for (int mt = 0; mt < 4; mt++)
#pragma unroll
                    for (int nt = 0; nt < 4; nt++)
                        mma_f16(acch[mt][nt], af[mt], bf[nt]);
            }
        }
    }

    gemm_epilogue(accz, acch, bz, bh, mBase, nBase, wr, wc, lane);
}

// ---------------- scan pass 1: per-chunk (A,B) summary (fp16 in, fp32 out) ---
__global__ __launch_bounds__(256)
void scan_pass1()
{
    const int g2 = blockIdx.x * 256 + threadIdx.x;   // (bc, d/2)
    const int bc = g2 >> 9;
    const int d0 = (g2 & 511) * 2;
    const size_t base = (size_t)bc * CHLEN * DD + d0;

    float2 Ar = make_float2(1.f, 1.f);
    float2 Br = make_float2(0.f, 0.f);
#pragma unroll 8
    for (int t = 0; t < CHLEN; t++) {
        const uint2 raw = *(const uint2*)&g_ab[base + (size_t)t * DD];
        const float2 ab0 = __half22float2(u32_to_h2(raw.x));
        const float2 ab1 = __half22float2(u32_to_h2(raw.y));
        Br.x = fmaf(ab0.x, Br.x, ab0.y); Ar.x *= ab0.x;
        Br.y = fmaf(ab1.x, Br.y, ab1.y); Ar.y *= ab1.x;
    }
    *(float2*)&g_Ac[(size_t)bc * DD + d0] = Ar;
    *(float2*)&g_Bc[(size_t)bc * DD + d0] = Br;
}

// ---------------- fused: chunk-prefix + scan + swish + LayerNorm -------------
__global__ __launch_bounds__(256)
void scan_ln_kernel(const float* __restrict__ swish_beta,
                    const float* __restrict__ gamma,
                    const float* __restrict__ lbeta,
                    float* __restrict__ out)
{
    const int bc = blockIdx.x;            // b*NCHUNK + chunk
    const int b = bc >> 5;
    const int chunk = bc & 31;
    const int tid = threadIdx.x;
    const int lane = tid & 31;
    const int w = tid >> 5;
    const int d0 = tid * 4;
    const float beta = __ldg(swish_beta);

    __shared__ float s1s[CHLEN][9], s2s[CHLEN][9];
    __shared__ float smu[CHLEN], sinv[CHLEN];

    // ---- hinit: prefix over predecessor chunk summaries ----
    float4 h = make_float4(0.f, 0.f, 0.f, 0.f);
    for (int c = 0; c < chunk; c++) {
        const size_t idx = (size_t)(b * NCHUNK + c) * DD + d0;
        const float4 A = *(const float4*)&g_Ac[idx];
        const float4 B = *(const float4*)&g_Bc[idx];
        h.x = fmaf(A.x, h.x, B.x);
        h.y = fmaf(A.y, h.y, B.y);
        h.z = fmaf(A.z, h.z, B.z);
        h.w = fmaf(A.w, h.w, B.w);
    }

    const size_t base = (size_t)(b * TT + chunk * CHLEN) * DD + d0;
    uint4 raw = *(const uint4*)&g_ab[base];

    // ---- Phase A: recurrence + swish; y->gmem fp16; warp sums->smem ----
    for (int t = 0; t < CHLEN; t++) {
        const float2 ab0 = __half22float2(u32_to_h2(raw.x));
        const float2 ab1 = __half22float2(u32_to_h2(raw.y));
        const float2 ab2 = __half22float2(u32_to_h2(raw.z));
        const float2 ab3 = __half22float2(u32_to_h2(raw.w));
        h.x = fmaf(ab0.x, h.x, ab0.y);
        h.y = fmaf(ab1.x, h.y, ab1.y);
        h.z = fmaf(ab2.x, h.z, ab2.y);
        h.w = fmaf(ab3.x, h.w, ab3.y);
        float4 y;
        {
            float s;
            s = beta * h.x; y.x = s * sigmoidf_fast(s);
            s = beta * h.y; y.y = s * sigmoidf_fast(s);
            s = beta * h.z; y.z = s * sigmoidf_fast(s);
            s = beta * h.w; y.w = s * sigmoidf_fast(s);
        }
        if (t + 1 < CHLEN)
            raw = *(const uint4*)&g_ab[base + (size_t)(t + 1) * DD];

        __half2 y0, y1;
        y0.x = __float2half_rn(y.x); y0.y = __float2half_rn(y.y);
        y1.x = __float2half_rn(y.z); y1.y = __float2half_rn(y.w);
        *(uint2*)&g_y16[base + (size_t)t * DD] =
            make_uint2(h2_to_u32(y0), h2_to_u32(y1));

        float s1 = y.x + y.y + y.z + y.w;
        float s2 = y.x * y.x + y.y * y.y + y.z * y.z + y.w * y.w;
#pragma unroll
        for (int o = 16; o > 0; o >>= 1) {
            s1 += __shfl_xor_sync(0xffffffffu, s1, o);
            s2 += __shfl_xor_sync(0xffffffffu, s2, o);
        }
        if (lane == 0) { s1s[t][w] = s1; s2s[t][w] = s2; }
    }
    __syncthreads();

    // finalize mu / inv per timestep (threads 0..63)
    if (tid < CHLEN) {
        float a1 = 0.0f, b1 = 0.0f;
#pragma unroll
        for (int j = 0; j < 8; j++) { a1 += s1s[tid][j]; b1 += s2s[tid][j]; }
        const float mu  = a1 * (1.0f / DD);
        const float var = b1 * (1.0f / DD) - mu * mu;
        smu[tid]  = mu;
        sinv[tid] = rsqrtf(var + 1e-5f);
    }
    __syncthreads();

    // ---- Phase B: normalize (y16 re-read is L2-resident) ----
    const float4 gm = *(const float4*)&gamma[d0];
    const float4 bt = *(const float4*)&lbeta[d0];
#pragma unroll 4
    for (int t = 0; t < CHLEN; t++) {
        const uint2 yr = *(const uint2*)&g_y16[base + (size_t)t * DD];
        const float2 ya = __half22float2(u32_to_h2(yr.x));
        const float2 yb = __half22float2(u32_to_h2(yr.y));
        const float mu  = smu[t];
        const float inv = sinv[t];
        float4 o;
        o.x = (ya.x - mu) * inv * gm.x + bt.x;
        o.y = (ya.y - mu) * inv * gm.y + bt.y;
        o.z = (yb.x - mu) * inv * gm.z + bt.z;
        o.w = (yb.y - mu) * inv * gm.w + bt.w;
        *(float4*)&out[base + (size_t)t * DD] = o;
    }
}

// ---------------- launch ----------------
extern "C" void kernel_launch(void* const* d_in, const int* in_sizes, int n_in,
                              void* d_out, int out_size)
{
    const float* x     = (const float*)d_in[0];
    const float* Wz    = (const float*)d_in[1];
    const float* bz    = (const float*)d_in[2];
    const float* Wh    = (const float*)d_in[3];
    const float* bh    = (const float*)d_in[4];
    const float* sbeta = (const float*)d_in[5];
    const float* gamma = (const float*)d_in[6];
    const float* lbeta = (const float*)d_in[7];
    float* out = (float*)d_out;

    convert_x_kernel<<<(MM * DD) / (256 * 4), 256>>>(x);
    transpose_kernel<<<dim3(32, 32, 2), 256>>>(Wz, Wh);

    dim3 gemmGrid(DD / 128, MM / 128);   // (8, 128)
    cudaError_t e = cudaFuncSetAttribute(
        gemm64_kernel, cudaFuncAttributeMaxDynamicSharedMemorySize, 2 * STAGE64);
    if (e == cudaSuccess) {
        gemm64_kernel<<<gemmGrid, 256, 2 * STAGE64>>>(bz, bh);
    } else {
        (void)cudaGetLastError();
        gemm32_kernel<<<gemmGrid, 256, 2 * STAGE32>>>(bz, bh);
    }

    scan_pass1<<<(BB * NCHUNK * DD) / (256 * 2), 256>>>();
    scan_ln_kernel<<<BB * NCHUNK, 256>>>(sbeta, gamma, lbeta, out);
}